// round 5
// baseline (speedup 1.0000x reference)
#include <cuda_runtime.h>
#include <cfloat>
#include <math.h>

#define BSZ 8
#define P1  8192
#define P2  2048
#define KNB 32
#define NQ  16384
#define NTOT 524288ull
#define SAMP 256

typedef unsigned long long ull;

__device__ int    g_nn[NQ*KNB];
__device__ float  g_bufA[64*NTOT];    // y1
__device__ float  g_bufB[64*NTOT];    // y2
__device__ float  g_mx[NQ*128];       // raw y3 per-query max
__device__ float  g_mn[NQ*128];       // raw y3 per-query min
__device__ double g_sum[128];
__device__ double g_sqsum[128];
__device__ float  g_scale[3][128];
__device__ float  g_shift[3][128];

static __device__ __forceinline__ ull pk2(float x, float y) {
    ull r; asm("mov.b64 %0,{%1,%2};" : "=l"(r) : "f"(x), "f"(y)); return r;
}
static __device__ __forceinline__ void upk2(ull v, float &x, float &y) {
    asm("mov.b64 {%0,%1},%2;" : "=f"(x), "=f"(y) : "l"(v));
}
static __device__ __forceinline__ void fma2(ull &acc, ull a, ull w) {
    asm("fma.rn.f32x2 %0,%1,%2,%0;" : "+l"(acc) : "l"(a), "l"(w));
}

// -------- KNN: warp per query, lane-sorted distributed top-32 --------
__global__ __launch_bounds__(1024) void knn_kernel(const float* __restrict__ xyz,
                           const int*   __restrict__ sidx,
                           float*       __restrict__ out_xyz) {
    extern __shared__ float4 pts[];                 // 128KB
    const int tid  = threadIdx.x;
    const int warp = tid >> 5, lane = tid & 31;
    const int qbase = blockIdx.x * 32;
    const int b = qbase / P2;
    const float* bx = xyz + (size_t)b * P1 * 3;

    for (int j = tid; j < P1; j += 1024) {
        float x = bx[3*j], y = bx[3*j+1], z = bx[3*j+2];
        float r2 = __fadd_rn(__fadd_rn(__fmul_rn(x,x), __fmul_rn(y,y)), __fmul_rn(z,z));
        pts[j] = make_float4(x, y, z, r2);
    }
    __syncthreads();

    const int q  = qbase + warp;
    const int si = sidx[q];
    const float qx = bx[3*si], qy = bx[3*si+1], qz = bx[3*si+2];
    const float rA = __fadd_rn(__fadd_rn(__fmul_rn(qx,qx), __fmul_rn(qy,qy)), __fmul_rn(qz,qz));
    if (lane < 3) out_xyz[(size_t)q*3 + lane] = (lane == 0) ? qx : (lane == 1 ? qy : qz);

    float best_d = FLT_MAX; int best_i = 0;   // ascending across lanes
    float thr = FLT_MAX;

    for (int j0 = 0; j0 < P1; j0 += 32) {
        float4 pt = pts[j0 + lane];
        float dot = __fmaf_rn(qz, pt.z, __fmaf_rn(qy, pt.y, __fmul_rn(qx, pt.x)));
        float d   = __fadd_rn(__fsub_rn(rA, __fmul_rn(2.f, dot)), pt.w);
        unsigned m = __ballot_sync(0xffffffffu, d < thr);
        while (m) {
            int src = __ffs(m) - 1; m &= m - 1;
            float dc = __shfl_sync(0xffffffffu, d, src);
            unsigned bal = __ballot_sync(0xffffffffu, dc < best_d);
            if (bal) {
                int pos  = __ffs(bal) - 1;
                float ud = __shfl_up_sync(0xffffffffu, best_d, 1);
                int   ui = __shfl_up_sync(0xffffffffu, best_i, 1);
                if (lane > pos)       { best_d = ud; best_i = ui; }
                else if (lane == pos) { best_d = dc; best_i = j0 + src; }
            }
        }
        thr = __shfl_sync(0xffffffffu, best_d, 31);
    }
    g_nn[(size_t)q*KNB + lane] = best_i;
}

// -------- conv (+prev BN affine+relu or gather) + BN stats (+ fused pool) --------
// tile: 256 samples x 64 outputs. 8 warps: h = w&1 (sample half), oq = w>>1 (16 outputs).
// acc packs OUTPUT pairs: acc[s][op] = (y[s][o], y[s][o+1]); samples duplicated via mov.
template<int CIN, int MODE, int POOL>
__global__ __launch_bounds__(256, 2) void layer_kernel(
                             const float* __restrict__ feat,
                             const float* __restrict__ xyz,
                             const float* __restrict__ qxyz,
                             const float* __restrict__ W,
                             const float* __restrict__ Bias,
                             const float* __restrict__ in,
                             float*       __restrict__ y_out,
                             int prev)
{
    extern __shared__ float smem[];
    float* a_sm = smem;                          // [CIN][256]
    ull*   w_sm = (ull*)(smem + CIN*SAMP);       // [CIN][32] natural (o,o+1) pairs

    const int tid    = threadIdx.x;
    const int o_base = blockIdx.y * 64;
    const size_t s0  = (size_t)blockIdx.x * SAMP;

    for (int i = tid; i < CIN*32; i += 256) {
        int op = i & 31, c = i >> 5;
        int o  = o_base + 2*op;
        w_sm[c*32 + op] = pk2(W[(size_t)o*CIN + c], W[(size_t)(o+1)*CIN + c]);
    }

    if (MODE == 0) {
        int n  = (int)s0 + tid;
        int b  = n >> 16;
        int qg = n >> 5;
        int nn = g_nn[n];
        const float4* frow = (const float4*)(feat + (size_t)(b*P1 + nn)*64);
        #pragma unroll
        for (int i = 0; i < 16; i++) {
            float4 f = frow[i];
            a_sm[(4*i+0)*SAMP + tid] = f.x;
            a_sm[(4*i+1)*SAMP + tid] = f.y;
            a_sm[(4*i+2)*SAMP + tid] = f.z;
            a_sm[(4*i+3)*SAMP + tid] = f.w;
        }
        const float* nx = xyz  + (size_t)(b*P1 + nn)*3;
        const float* qp = qxyz + (size_t)qg*3;
        a_sm[64*SAMP + tid] = __fsub_rn(nx[0], qp[0]);
        a_sm[65*SAMP + tid] = __fsub_rn(nx[1], qp[1]);
        a_sm[66*SAMP + tid] = __fsub_rn(nx[2], qp[2]);
    } else {
        const float* sc = g_scale[prev];
        const float* sh = g_shift[prev];
        for (int i = tid; i < CIN*64; i += 256) {
            int c = i >> 6, s4 = (i & 63) * 4;
            float4 v = *(const float4*)(in + (size_t)c*NTOT + s0 + s4);
            float s_ = sc[c], h_ = sh[c];
            v.x = fmaxf(__fmaf_rn(s_, v.x, h_), 0.f);
            v.y = fmaxf(__fmaf_rn(s_, v.y, h_), 0.f);
            v.z = fmaxf(__fmaf_rn(s_, v.z, h_), 0.f);
            v.w = fmaxf(__fmaf_rn(s_, v.w, h_), 0.f);
            *(float4*)(a_sm + c*SAMP + s4) = v;
        }
    }
    __syncthreads();

    const int w  = tid >> 5, lane = tid & 31;
    const int h  = w & 1;          // sample half
    const int oq = w >> 1;         // output quarter (16 channels)
    const float* ap0 = a_sm + h*128 + 4*lane;
    const ulonglong2* wp0 = (const ulonglong2*)(w_sm + oq*8);

    ull acc[4][8];
    #pragma unroll
    for (int op = 0; op < 8; op++) {
        int o = o_base + oq*16 + 2*op;
        ull b2 = pk2(Bias[o], Bias[o+1]);
        #pragma unroll
        for (int s = 0; s < 4; s++) acc[s][op] = b2;
    }

    float4 av = *(const float4*)ap0;
    ulonglong2 wv0 = wp0[0], wv1 = wp0[1], wv2 = wp0[2], wv3 = wp0[3];

    for (int c = 0; c < CIN; c++) {
        int cn = (c + 1 < CIN) ? c + 1 : c;
        float4 avn = *(const float4*)(ap0 + cn*SAMP);
        const ulonglong2* wpn = (const ulonglong2*)((const ull*)wp0 + cn*32);
        ulonglong2 wn0 = wpn[0], wn1 = wpn[1], wn2 = wpn[2], wn3 = wpn[3];

        ull ad[4];
        ad[0] = pk2(av.x, av.x); ad[1] = pk2(av.y, av.y);
        ad[2] = pk2(av.z, av.z); ad[3] = pk2(av.w, av.w);
        #pragma unroll
        for (int s = 0; s < 4; s++) {
            fma2(acc[s][0], ad[s], wv0.x);
            fma2(acc[s][1], ad[s], wv0.y);
            fma2(acc[s][2], ad[s], wv1.x);
            fma2(acc[s][3], ad[s], wv1.y);
            fma2(acc[s][4], ad[s], wv2.x);
            fma2(acc[s][5], ad[s], wv2.y);
            fma2(acc[s][6], ad[s], wv3.x);
            fma2(acc[s][7], ad[s], wv3.y);
        }
        av = avn; wv0 = wn0; wv1 = wn1; wv2 = wn2; wv3 = wn3;
    }

    #pragma unroll
    for (int op = 0; op < 8; op++) {
        int o = o_base + oq*16 + 2*op;
        float lo[4], hi[4];
        #pragma unroll
        for (int s = 0; s < 4; s++) upk2(acc[s][op], lo[s], hi[s]);

        float sl = (lo[0]+lo[1])+(lo[2]+lo[3]);
        float sh_ = (hi[0]+hi[1])+(hi[2]+hi[3]);
        float ql = (lo[0]*lo[0]+lo[1]*lo[1])+(lo[2]*lo[2]+lo[3]*lo[3]);
        float qh = (hi[0]*hi[0]+hi[1]*hi[1])+(hi[2]*hi[2]+hi[3]*hi[3]);
        #pragma unroll
        for (int off = 16; off; off >>= 1) {
            sl  += __shfl_xor_sync(0xffffffffu, sl,  off);
            sh_ += __shfl_xor_sync(0xffffffffu, sh_, off);
            ql  += __shfl_xor_sync(0xffffffffu, ql,  off);
            qh  += __shfl_xor_sync(0xffffffffu, qh,  off);
        }
        if (lane == 0) {
            atomicAdd(&g_sum[o],     (double)sl);
            atomicAdd(&g_sum[o+1],   (double)sh_);
            atomicAdd(&g_sqsum[o],   (double)ql);
            atomicAdd(&g_sqsum[o+1], (double)qh);
        }

        if (POOL) {
            float mxl = fmaxf(fmaxf(lo[0],lo[1]), fmaxf(lo[2],lo[3]));
            float mnl = fminf(fminf(lo[0],lo[1]), fminf(lo[2],lo[3]));
            float mxh = fmaxf(fmaxf(hi[0],hi[1]), fmaxf(hi[2],hi[3]));
            float mnh = fminf(fminf(hi[0],hi[1]), fminf(hi[2],hi[3]));
            #pragma unroll
            for (int off = 4; off; off >>= 1) {
                mxl = fmaxf(mxl, __shfl_xor_sync(0xffffffffu, mxl, off));
                mnl = fminf(mnl, __shfl_xor_sync(0xffffffffu, mnl, off));
                mxh = fmaxf(mxh, __shfl_xor_sync(0xffffffffu, mxh, off));
                mnh = fminf(mnh, __shfl_xor_sync(0xffffffffu, mnh, off));
            }
            if ((lane & 7) == 0) {
                int q = (int)(s0 >> 5) + 4*h + (lane >> 3);
                g_mx[(size_t)q*128 + o]   = mxl;
                g_mn[(size_t)q*128 + o]   = mnl;
                g_mx[(size_t)q*128 + o+1] = mxh;
                g_mn[(size_t)q*128 + o+1] = mnh;
            }
        } else {
            size_t base = s0 + 128*h + 4*lane;
            *(float4*)(y_out + (size_t)o*NTOT + base)     = make_float4(lo[0], lo[1], lo[2], lo[3]);
            *(float4*)(y_out + (size_t)(o+1)*NTOT + base) = make_float4(hi[0], hi[1], hi[2], hi[3]);
        }
    }
}

// -------- BN finalize --------
__global__ void finalize_kernel(const float* __restrict__ gamma,
                                const float* __restrict__ beta,
                                int layer) {
    int o = threadIdx.x;
    double mean = g_sum[o]   * (1.0 / (double)NTOT);
    double var  = g_sqsum[o] * (1.0 / (double)NTOT) - mean*mean;
    float sc = gamma[o] * (float)(1.0 / sqrt(var + 1e-5));
    g_scale[layer][o] = sc;
    g_shift[layer][o] = __fmaf_rn(-(float)mean, sc, beta[o]);
    g_sum[o] = 0.0; g_sqsum[o] = 0.0;
}

// -------- final: affine+relu on pooled max/min (monotone trick) --------
__global__ void pool_apply_kernel(float* __restrict__ out) {
    int idx = blockIdx.x * 256 + threadIdx.x;
    int o = idx & 127;
    float sc = g_scale[2][o], sh = g_shift[2][o];
    float vmx = __fmaf_rn(sc, g_mx[idx], sh);
    float vmn = __fmaf_rn(sc, g_mn[idx], sh);
    out[idx] = fmaxf(fmaxf(vmx, vmn), 0.f);
}

extern "C" void kernel_launch(void* const* d_in, const int* in_sizes, int n_in,
                              void* d_out, int out_size) {
    const float* xyz  = (const float*)d_in[0];
    const float* feat = (const float*)d_in[1];
    const int*   sidx = (const int*)d_in[2];
    const float *w1=(const float*)d_in[3],  *b1=(const float*)d_in[4],
                *g1=(const float*)d_in[5],  *t1=(const float*)d_in[6];
    const float *w2=(const float*)d_in[7],  *b2=(const float*)d_in[8],
                *g2=(const float*)d_in[9],  *t2=(const float*)d_in[10];
    const float *w3=(const float*)d_in[11], *b3=(const float*)d_in[12],
                *g3=(const float*)d_in[13], *t3=(const float*)d_in[14];
    float* out      = (float*)d_out;
    float* new_xyz  = out;
    float* new_feat = out + NQ*3;

    float* bufA; cudaGetSymbolAddress((void**)&bufA, g_bufA);
    float* bufB; cudaGetSymbolAddress((void**)&bufB, g_bufB);

    const int S1 = 67*SAMP*4 + 67*32*8;    // 85760
    const int S2 = 64*SAMP*4 + 64*32*8;    // 81920
    cudaFuncSetAttribute(knn_kernel, cudaFuncAttributeMaxDynamicSharedMemorySize, 131072);
    cudaFuncSetAttribute(layer_kernel<67,0,0>, cudaFuncAttributeMaxDynamicSharedMemorySize, S1);
    cudaFuncSetAttribute(layer_kernel<64,1,0>, cudaFuncAttributeMaxDynamicSharedMemorySize, S2);
    cudaFuncSetAttribute(layer_kernel<64,1,1>, cudaFuncAttributeMaxDynamicSharedMemorySize, S2);

    knn_kernel<<<NQ/32, 1024, 131072>>>(xyz, sidx, new_xyz);
    layer_kernel<67,0,0><<<dim3(NTOT/SAMP,1), 256, S1>>>(feat, xyz, new_xyz, w1, b1, nullptr, bufA, 0);
    finalize_kernel<<<1,64>>>(g1, t1, 0);
    layer_kernel<64,1,0><<<dim3(NTOT/SAMP,1), 256, S2>>>(nullptr, nullptr, nullptr, w2, b2, bufA, bufB, 0);
    finalize_kernel<<<1,64>>>(g2, t2, 1);
    layer_kernel<64,1,1><<<dim3(NTOT/SAMP,2), 256, S2>>>(nullptr, nullptr, nullptr, w3, b3, bufB, nullptr, 1);
    finalize_kernel<<<1,128>>>(g3, t3, 2);
    pool_apply_kernel<<<(NQ*128)/256, 256>>>(new_feat);
}

// round 7
// speedup vs baseline: 1.4837x; 1.4837x over previous
#include <cuda_runtime.h>
#include <cuda_bf16.h>
#include <cfloat>
#include <math.h>
#include <cstdint>

#define BSZ 8
#define P1  8192
#define P2  2048
#define KNB 32
#define NQ  16384
#define NTOT 524288ull

typedef unsigned long long ull;

__device__ int    g_nn[NQ*KNB];
__device__ float  g_bufA[NTOT*128];   // y1 [n][64], later y3 [n][128]
__device__ float  g_bufB[NTOT*64];    // y2 [n][64]
__device__ float  g_mx[NQ*128];
__device__ float  g_mn[NQ*128];
__device__ double g_sum[128];
__device__ double g_sqsum[128];
__device__ float  g_scale[3][128];
__device__ float  g_shift[3][128];

static __device__ __forceinline__ uint32_t smem_u32(const void* p) {
    uint32_t a; asm("{ .reg .u64 t; cvta.to.shared.u64 t, %1; cvt.u32.u64 %0, t; }" : "=r"(a) : "l"(p));
    return a;
}
static __device__ __forceinline__ void ldsm4(uint32_t* r, uint32_t a) {
    asm volatile("ldmatrix.sync.aligned.m8n8.x4.shared.b16 {%0,%1,%2,%3}, [%4];"
        : "=r"(r[0]), "=r"(r[1]), "=r"(r[2]), "=r"(r[3]) : "r"(a));
}
static __device__ __forceinline__ void ldsm2(uint32_t* r, uint32_t a) {
    asm volatile("ldmatrix.sync.aligned.m8n8.x2.shared.b16 {%0,%1}, [%2];"
        : "=r"(r[0]), "=r"(r[1]) : "r"(a));
}
static __device__ __forceinline__ void mma16816(float* d, const uint32_t* a, const uint32_t* b) {
    asm volatile("mma.sync.aligned.m16n8k16.row.col.f32.bf16.bf16.f32 "
        "{%0,%1,%2,%3},{%4,%5,%6,%7},{%8,%9},{%0,%1,%2,%3};"
        : "+f"(d[0]), "+f"(d[1]), "+f"(d[2]), "+f"(d[3])
        : "r"(a[0]), "r"(a[1]), "r"(a[2]), "r"(a[3]), "r"(b[0]), "r"(b[1]));
}
static __device__ __forceinline__ uint32_t pkbf(float a, float b) {
    return (uint32_t)__bfloat16_as_ushort(__float2bfloat16_rn(a))
         | ((uint32_t)__bfloat16_as_ushort(__float2bfloat16_rn(b)) << 16);
}
static __device__ __forceinline__ void split1(float v, __nv_bfloat16 &h, __nv_bfloat16 &l) {
    h = __float2bfloat16_rn(v);
    l = __float2bfloat16_rn(v - __bfloat162float(h));
}
static __device__ __forceinline__ void split4(float4 v, uint2 &H, uint2 &L) {
    __nv_bfloat16 hx, hy, hz, hw, lx, ly, lz, lw;
    split1(v.x, hx, lx); split1(v.y, hy, ly);
    split1(v.z, hz, lz); split1(v.w, hw, lw);
    H.x = (uint32_t)__bfloat16_as_ushort(hx) | ((uint32_t)__bfloat16_as_ushort(hy) << 16);
    H.y = (uint32_t)__bfloat16_as_ushort(hz) | ((uint32_t)__bfloat16_as_ushort(hw) << 16);
    L.x = (uint32_t)__bfloat16_as_ushort(lx) | ((uint32_t)__bfloat16_as_ushort(ly) << 16);
    L.y = (uint32_t)__bfloat16_as_ushort(lz) | ((uint32_t)__bfloat16_as_ushort(lw) << 16);
}

// -------- KNN: warp per query, lane-sorted distributed top-32 --------
__global__ __launch_bounds__(1024) void knn_kernel(const float* __restrict__ xyz,
                           const int*   __restrict__ sidx,
                           float*       __restrict__ out_xyz) {
    extern __shared__ float4 pts[];
    const int tid  = threadIdx.x;
    const int warp = tid >> 5, lane = tid & 31;
    const int qbase = blockIdx.x * 32;
    const int b = qbase / P2;
    const float* bx = xyz + (size_t)b * P1 * 3;

    for (int j = tid; j < P1; j += 1024) {
        float x = bx[3*j], y = bx[3*j+1], z = bx[3*j+2];
        float r2 = __fadd_rn(__fadd_rn(__fmul_rn(x,x), __fmul_rn(y,y)), __fmul_rn(z,z));
        pts[j] = make_float4(x, y, z, r2);
    }
    __syncthreads();

    const int q  = qbase + warp;
    const int si = sidx[q];
    const float qx = bx[3*si], qy = bx[3*si+1], qz = bx[3*si+2];
    const float rA = __fadd_rn(__fadd_rn(__fmul_rn(qx,qx), __fmul_rn(qy,qy)), __fmul_rn(qz,qz));
    if (lane < 3) out_xyz[(size_t)q*3 + lane] = (lane == 0) ? qx : (lane == 1 ? qy : qz);

    float best_d = FLT_MAX; int best_i = 0;
    float thr = FLT_MAX;

    for (int j0 = 0; j0 < P1; j0 += 32) {
        float4 pt = pts[j0 + lane];
        float dot = __fmaf_rn(qz, pt.z, __fmaf_rn(qy, pt.y, __fmul_rn(qx, pt.x)));
        float d   = __fadd_rn(__fsub_rn(rA, __fmul_rn(2.f, dot)), pt.w);
        unsigned m = __ballot_sync(0xffffffffu, d < thr);
        while (m) {
            int src = __ffs(m) - 1; m &= m - 1;
            float dc = __shfl_sync(0xffffffffu, d, src);
            unsigned bal = __ballot_sync(0xffffffffu, dc < best_d);
            if (bal) {
                int pos  = __ffs(bal) - 1;
                float ud = __shfl_up_sync(0xffffffffu, best_d, 1);
                int   ui = __shfl_up_sync(0xffffffffu, best_i, 1);
                if (lane > pos)       { best_d = ud; best_i = ui; }
                else if (lane == pos) { best_d = dc; best_i = j0 + src; }
            }
        }
        thr = __shfl_sync(0xffffffffu, best_d, 31);
    }
    g_nn[(size_t)q*KNB + lane] = best_i;
}

// -------- GEMM layer via mma.sync bf16 (3-term split), M=128/CTA --------
// smem: A_hi/A_lo [128][ST] bf16, B_hi/B_lo [N][ST] bf16, ST = KPAD+8 (conflict-free ldmatrix)
template<int KPAD, int CIN, int N, int MODE>
__global__ __launch_bounds__(256) void gemm_kernel(
        const float* __restrict__ feat, const float* __restrict__ xyz,
        const float* __restrict__ qxyz, const float* __restrict__ y_in,
        const float* __restrict__ W,    float* __restrict__ y_out, int prev)
{
    extern __shared__ char smem[];
    constexpr int ST = KPAD + 8;
    constexpr int OFF_AH = 0;
    constexpr int OFF_AL = 128*ST*2;
    constexpr int OFF_BH = 2*OFF_AL;
    constexpr int OFF_BL = OFF_BH + N*ST*2;
    const uint32_t sb = smem_u32(smem);
    const int tid = threadIdx.x;
    const int n0  = blockIdx.x * 128;
    const int cq  = tid & 15, rs = tid >> 4;

    if (MODE == 0) {
        // zero pad cols 64..KPAD-1 of A (128 rows) and B (N rows)
        uint4 z = make_uint4(0,0,0,0);
        if (tid < 128 + N) {
            int isA = tid < 128;
            int row = isA ? tid : tid - 128;
            char* base = smem + (isA ? OFF_AH : OFF_BH) + row*ST*2 + 128;
            char* basl = smem + (isA ? OFF_AL : OFF_BL) + row*ST*2 + 128;
            *(uint4*)(base) = z;      *(uint4*)(base + 16) = z;
            *(uint4*)(basl) = z;      *(uint4*)(basl + 16) = z;
        }
    }

    if (MODE == 0) {
        #pragma unroll
        for (int it = 0; it < 8; it++) {
            int row = rs + 16*it;
            int n   = n0 + row;
            int b   = n >> 16;
            int nn  = g_nn[n];
            float4 f = *(const float4*)(feat + (size_t)(b*P1 + nn)*64 + 4*cq);
            uint2 H, L; split4(f, H, L);
            *(uint2*)(smem + OFF_AH + row*ST*2 + 8*cq) = H;
            *(uint2*)(smem + OFF_AL + row*ST*2 + 8*cq) = L;
            if (cq == 0) {
                int q = n >> 5;
                const float* nx = xyz  + (size_t)(b*P1 + nn)*3;
                const float* qp = qxyz + (size_t)q*3;
                #pragma unroll
                for (int j = 0; j < 3; j++) {
                    __nv_bfloat16 h, l; split1(__fsub_rn(nx[j], qp[j]), h, l);
                    *(__nv_bfloat16*)(smem + OFF_AH + row*ST*2 + 128 + 2*j) = h;
                    *(__nv_bfloat16*)(smem + OFF_AL + row*ST*2 + 128 + 2*j) = l;
                }
            }
        }
        #pragma unroll
        for (int it = 0; it < N/16; it++) {
            int o = rs + 16*it;
            const float* wr = W + (size_t)o*CIN;
            float4 w4 = make_float4(wr[4*cq], wr[4*cq+1], wr[4*cq+2], wr[4*cq+3]);
            uint2 H, L; split4(w4, H, L);
            *(uint2*)(smem + OFF_BH + o*ST*2 + 8*cq) = H;
            *(uint2*)(smem + OFF_BL + o*ST*2 + 8*cq) = L;
            if (cq == 0) {
                #pragma unroll
                for (int j = 0; j < 3; j++) {
                    __nv_bfloat16 h, l; split1(wr[64 + j], h, l);
                    *(__nv_bfloat16*)(smem + OFF_BH + o*ST*2 + 128 + 2*j) = h;
                    *(__nv_bfloat16*)(smem + OFF_BL + o*ST*2 + 128 + 2*j) = l;
                }
            }
        }
    } else {
        const float4 sc4 = *(const float4*)(g_scale[prev] + 4*cq);
        const float4 sh4 = *(const float4*)(g_shift[prev] + 4*cq);
        #pragma unroll
        for (int it = 0; it < 8; it++) {
            int row = rs + 16*it;
            float4 v = *(const float4*)(y_in + (size_t)(n0 + row)*64 + 4*cq);
            v.x = fmaxf(__fmaf_rn(sc4.x, v.x, sh4.x), 0.f);
            v.y = fmaxf(__fmaf_rn(sc4.y, v.y, sh4.y), 0.f);
            v.z = fmaxf(__fmaf_rn(sc4.z, v.z, sh4.z), 0.f);
            v.w = fmaxf(__fmaf_rn(sc4.w, v.w, sh4.w), 0.f);
            uint2 H, L; split4(v, H, L);
            *(uint2*)(smem + OFF_AH + row*ST*2 + 8*cq) = H;
            *(uint2*)(smem + OFF_AL + row*ST*2 + 8*cq) = L;
        }
        #pragma unroll
        for (int it = 0; it < N/16; it++) {
            int o = rs + 16*it;
            float4 w4 = *(const float4*)(W + (size_t)o*64 + 4*cq);
            uint2 H, L; split4(w4, H, L);
            *(uint2*)(smem + OFF_BH + o*ST*2 + 8*cq) = H;
            *(uint2*)(smem + OFF_BL + o*ST*2 + 8*cq) = L;
        }
    }
    __syncthreads();

    const int w = tid >> 5, lane = tid & 31;
    const int mw = w & 3, nw = w >> 2;          // warp tile: m32 x n(N/2)
    constexpr int NB = N/16;                     // n8 blocks per warp

    float acc[2][NB][4];
    #pragma unroll
    for (int mh = 0; mh < 2; mh++)
        #pragma unroll
        for (int nb = 0; nb < NB; nb++)
            #pragma unroll
            for (int j = 0; j < 4; j++) acc[mh][nb][j] = 0.f;

    const uint32_t aoff = ((mw*32 + (lane & 15))*ST + (lane >> 4)*8) * 2;
    const uint32_t boff = ((nw*(N/2) + (lane & 7))*ST + ((lane >> 3) & 1)*8) * 2;

    #pragma unroll
    for (int kk = 0; kk < KPAD/16; kk++) {
        uint32_t ah[2][4], al[2][4];
        #pragma unroll
        for (int mh = 0; mh < 2; mh++) {
            ldsm4(ah[mh], sb + OFF_AH + aoff + (mh*16*ST + kk*16)*2);
            ldsm4(al[mh], sb + OFF_AL + aoff + (mh*16*ST + kk*16)*2);
        }
        #pragma unroll
        for (int nb = 0; nb < NB; nb++) {
            uint32_t bh[2], bl[2];
            ldsm2(bh, sb + OFF_BH + boff + (nb*8*ST + kk*16)*2);
            ldsm2(bl, sb + OFF_BL + boff + (nb*8*ST + kk*16)*2);
            #pragma unroll
            for (int mh = 0; mh < 2; mh++) {
                mma16816(acc[mh][nb], ah[mh], bh);
                mma16816(acc[mh][nb], ah[mh], bl);
                mma16816(acc[mh][nb], al[mh], bh);
            }
        }
    }

    const int g = lane >> 2, t = lane & 3;
    #pragma unroll
    for (int mh = 0; mh < 2; mh++) {
        #pragma unroll
        for (int nb = 0; nb < NB; nb++) {
            int row = n0 + mw*32 + mh*16 + g;
            int col = nw*(N/2) + nb*8 + 2*t;
            *(float2*)(y_out + (size_t)row*N + col)       = make_float2(acc[mh][nb][0], acc[mh][nb][1]);
            *(float2*)(y_out + (size_t)(row + 8)*N + col) = make_float2(acc[mh][nb][2], acc[mh][nb][3]);
        }
    }
}

// -------- per-channel stats over raw y [NTOT][64] --------
__global__ __launch_bounds__(256) void stats_kernel(const float* __restrict__ y) {
    __shared__ float st[8][16][8];
    const int tid = threadIdx.x, cq = tid & 15, slane = tid >> 4;
    const int w = tid >> 5, lane = tid & 31;
    float4 s4 = make_float4(0,0,0,0), q4 = make_float4(0,0,0,0);
    size_t base = (size_t)blockIdx.x * 512;
    for (int it = 0; it < 32; it++) {
        float4 v = *(const float4*)(y + (base + slane + 16*it)*64 + 4*cq);
        s4.x += v.x; s4.y += v.y; s4.z += v.z; s4.w += v.w;
        q4.x += v.x*v.x; q4.y += v.y*v.y; q4.z += v.z*v.z; q4.w += v.w*v.w;
    }
    float vals[8] = {s4.x, s4.y, s4.z, s4.w, q4.x, q4.y, q4.z, q4.w};
    #pragma unroll
    for (int j = 0; j < 8; j++) vals[j] += __shfl_xor_sync(0xffffffffu, vals[j], 16);
    if (lane < 16) {
        #pragma unroll
        for (int j = 0; j < 8; j++) st[w][lane][j] = vals[j];
    }
    __syncthreads();
    if (tid < 128) {
        int c4 = tid >> 3, v = tid & 7;
        float acc = 0.f;
        #pragma unroll
        for (int ww = 0; ww < 8; ww++) acc += st[ww][c4][v];
        int ch = 4*c4 + (v & 3);
        atomicAdd((v < 4) ? &g_sum[ch] : &g_sqsum[ch], (double)acc);
    }
}

// -------- L3: pool (max/min of raw y3 per query) + stats --------
__global__ __launch_bounds__(256) void pool_stats_kernel(const float* __restrict__ y3) {
    __shared__ float ssum[256], ssq[256];
    const int tid = threadIdx.x, c = tid & 127, h = tid >> 7;
    float s = 0.f, qq = 0.f;
    #pragma unroll
    for (int j = 0; j < 4; j++) {
        int q = blockIdx.x*8 + 4*h + j;
        const float* p = y3 + (size_t)q*KNB*128 + c;
        float mx = -FLT_MAX, mn = FLT_MAX;
        #pragma unroll 4
        for (int smp = 0; smp < 32; smp++) {
            float v = p[(size_t)smp*128];
            mx = fmaxf(mx, v); mn = fminf(mn, v);
            s += v; qq += v*v;
        }
        g_mx[(size_t)q*128 + c] = mx;
        g_mn[(size_t)q*128 + c] = mn;
    }
    ssum[tid] = s; ssq[tid] = qq;
    __syncthreads();
    if (tid < 128) {
        atomicAdd(&g_sum[c],   (double)(ssum[tid] + ssum[tid+128]));
        atomicAdd(&g_sqsum[c], (double)(ssq[tid]  + ssq[tid+128]));
    }
}

// -------- BN finalize (bias absorbed by mean subtraction) --------
__global__ void finalize_kernel(const float* __restrict__ gamma,
                                const float* __restrict__ beta,
                                int layer) {
    int o = threadIdx.x;
    double mean = g_sum[o]   * (1.0 / (double)NTOT);
    double var  = g_sqsum[o] * (1.0 / (double)NTOT) - mean*mean;
    float sc = gamma[o] * (float)(1.0 / sqrt(var + 1e-5));
    g_scale[layer][o] = sc;
    g_shift[layer][o] = __fmaf_rn(-(float)mean, sc, beta[o]);
    g_sum[o] = 0.0; g_sqsum[o] = 0.0;
}

// -------- final affine+relu on pooled max/min --------
__global__ void pool_apply_kernel(float* __restrict__ out) {
    int idx = blockIdx.x * 256 + threadIdx.x;
    int o = idx & 127;
    float sc = g_scale[2][o], sh = g_shift[2][o];
    float vmx = __fmaf_rn(sc, g_mx[idx], sh);
    float vmn = __fmaf_rn(sc, g_mn[idx], sh);
    out[idx] = fmaxf(fmaxf(vmx, vmn), 0.f);
}

extern "C" void kernel_launch(void* const* d_in, const int* in_sizes, int n_in,
                              void* d_out, int out_size) {
    const float* xyz  = (const float*)d_in[0];
    const float* feat = (const float*)d_in[1];
    const int*   sidx = (const int*)d_in[2];
    const float *w1=(const float*)d_in[3],
                *g1=(const float*)d_in[5],  *t1=(const float*)d_in[6];
    const float *w2=(const float*)d_in[7],
                *g2=(const float*)d_in[9],  *t2=(const float*)d_in[10];
    const float *w3=(const float*)d_in[11],
                *g3=(const float*)d_in[13], *t3=(const float*)d_in[14];
    float* out      = (float*)d_out;
    float* new_xyz  = out;
    float* new_feat = out + NQ*3;

    float* bufA; cudaGetSymbolAddress((void**)&bufA, g_bufA);
    float* bufB; cudaGetSymbolAddress((void**)&bufB, g_bufB);

    const int S1 = (256 + 128) * (80+8) * 2;   // 67584
    const int S2 = (256 + 128) * (64+8) * 2;   // 55296
    const int S3 = (256 + 256) * (64+8) * 2;   // 73728
    cudaFuncSetAttribute(knn_kernel, cudaFuncAttributeMaxDynamicSharedMemorySize, 131072);
    cudaFuncSetAttribute(gemm_kernel<80,67,64,0>,  cudaFuncAttributeMaxDynamicSharedMemorySize, S1);
    cudaFuncSetAttribute(gemm_kernel<64,64,64,1>,  cudaFuncAttributeMaxDynamicSharedMemorySize, S2);
    cudaFuncSetAttribute(gemm_kernel<64,64,128,1>, cudaFuncAttributeMaxDynamicSharedMemorySize, S3);

    knn_kernel<<<NQ/32, 1024, 131072>>>(xyz, sidx, new_xyz);
    gemm_kernel<80,67,64,0><<<NTOT/128, 256, S1>>>(feat, xyz, new_xyz, nullptr, w1, bufA, 0);
    stats_kernel<<<1024, 256>>>(bufA);
    finalize_kernel<<<1,64>>>(g1, t1, 0);
    gemm_kernel<64,64,64,1><<<NTOT/128, 256, S2>>>(nullptr, nullptr, nullptr, bufA, w2, bufB, 0);
    stats_kernel<<<1024, 256>>>(bufB);
    finalize_kernel<<<1,64>>>(g2, t2, 1);
    gemm_kernel<64,64,128,1><<<NTOT/128, 256, S3>>>(nullptr, nullptr, nullptr, bufB, w3, bufA, 1);
    pool_stats_kernel<<<NQ/8, 256>>>(bufA);
    finalize_kernel<<<1,128>>>(g3, t3, 2);
    pool_apply_kernel<<<(NQ*128)/256, 256>>>(new_feat);
}

// round 8
// speedup vs baseline: 1.7514x; 1.1804x over previous
#include <cuda_runtime.h>
#include <cuda_bf16.h>
#include <cfloat>
#include <math.h>
#include <cstdint>

#define BSZ 8
#define P1  8192
#define P2  2048
#define KNB 32
#define NQ  16384
#define NTOT 524288ull

typedef unsigned long long ull;

__device__ int    g_nn[NQ*KNB];
__device__ float  g_bufA[NTOT*64];    // y1 [n][64]
__device__ float  g_bufB[NTOT*64];    // y2 [n][64]
__device__ float  g_mx[NQ*128];
__device__ float  g_mn[NQ*128];
__device__ double g_sum[128];
__device__ double g_sqsum[128];
__device__ float  g_scale[3][128];
__device__ float  g_shift[3][128];

static __device__ __forceinline__ uint32_t smem_u32(const void* p) {
    uint32_t a; asm("{ .reg .u64 t; cvta.to.shared.u64 t, %1; cvt.u32.u64 %0, t; }" : "=r"(a) : "l"(p));
    return a;
}
static __device__ __forceinline__ void ldsm4(uint32_t* r, uint32_t a) {
    asm volatile("ldmatrix.sync.aligned.m8n8.x4.shared.b16 {%0,%1,%2,%3}, [%4];"
        : "=r"(r[0]), "=r"(r[1]), "=r"(r[2]), "=r"(r[3]) : "r"(a));
}
static __device__ __forceinline__ void ldsm2(uint32_t* r, uint32_t a) {
    asm volatile("ldmatrix.sync.aligned.m8n8.x2.shared.b16 {%0,%1}, [%2];"
        : "=r"(r[0]), "=r"(r[1]) : "r"(a));
}
static __device__ __forceinline__ void mma16816(float* d, const uint32_t* a, const uint32_t* b) {
    asm volatile("mma.sync.aligned.m16n8k16.row.col.f32.bf16.bf16.f32 "
        "{%0,%1,%2,%3},{%4,%5,%6,%7},{%8,%9},{%0,%1,%2,%3};"
        : "+f"(d[0]), "+f"(d[1]), "+f"(d[2]), "+f"(d[3])
        : "r"(a[0]), "r"(a[1]), "r"(a[2]), "r"(a[3]), "r"(b[0]), "r"(b[1]));
}
static __device__ __forceinline__ void split1(float v, __nv_bfloat16 &h, __nv_bfloat16 &l) {
    h = __float2bfloat16_rn(v);
    l = __float2bfloat16_rn(v - __bfloat162float(h));
}
static __device__ __forceinline__ void split4(float4 v, uint2 &H, uint2 &L) {
    __nv_bfloat16 hx, hy, hz, hw, lx, ly, lz, lw;
    split1(v.x, hx, lx); split1(v.y, hy, ly);
    split1(v.z, hz, lz); split1(v.w, hw, lw);
    H.x = (uint32_t)__bfloat16_as_ushort(hx) | ((uint32_t)__bfloat16_as_ushort(hy) << 16);
    H.y = (uint32_t)__bfloat16_as_ushort(hz) | ((uint32_t)__bfloat16_as_ushort(hw) << 16);
    L.x = (uint32_t)__bfloat16_as_ushort(lx) | ((uint32_t)__bfloat16_as_ushort(ly) << 16);
    L.y = (uint32_t)__bfloat16_as_ushort(lz) | ((uint32_t)__bfloat16_as_ushort(lw) << 16);
}

// -------- KNN: warp per query, lane-sorted distributed top-32 --------
__global__ __launch_bounds__(1024) void knn_kernel(const float* __restrict__ xyz,
                           const int*   __restrict__ sidx,
                           float*       __restrict__ out_xyz) {
    extern __shared__ float4 pts[];
    const int tid  = threadIdx.x;
    const int warp = tid >> 5, lane = tid & 31;
    const int qbase = blockIdx.x * 32;
    const int b = qbase / P2;
    const float* bx = xyz + (size_t)b * P1 * 3;

    for (int j = tid; j < P1; j += 1024) {
        float x = bx[3*j], y = bx[3*j+1], z = bx[3*j+2];
        float r2 = __fadd_rn(__fadd_rn(__fmul_rn(x,x), __fmul_rn(y,y)), __fmul_rn(z,z));
        pts[j] = make_float4(x, y, z, r2);
    }
    __syncthreads();

    const int q  = qbase + warp;
    const int si = sidx[q];
    const float qx = bx[3*si], qy = bx[3*si+1], qz = bx[3*si+2];
    const float rA = __fadd_rn(__fadd_rn(__fmul_rn(qx,qx), __fmul_rn(qy,qy)), __fmul_rn(qz,qz));
    if (lane < 3) out_xyz[(size_t)q*3 + lane] = (lane == 0) ? qx : (lane == 1 ? qy : qz);

    float best_d = FLT_MAX; int best_i = 0;
    float thr = FLT_MAX;

    for (int j0 = 0; j0 < P1; j0 += 32) {
        float4 pt = pts[j0 + lane];
        float dot = __fmaf_rn(qz, pt.z, __fmaf_rn(qy, pt.y, __fmul_rn(qx, pt.x)));
        float d   = __fadd_rn(__fsub_rn(rA, __fmul_rn(2.f, dot)), pt.w);
        unsigned m = __ballot_sync(0xffffffffu, d < thr);
        while (m) {
            int src = __ffs(m) - 1; m &= m - 1;
            float dc = __shfl_sync(0xffffffffu, d, src);
            unsigned bal = __ballot_sync(0xffffffffu, dc < best_d);
            if (bal) {
                int pos  = __ffs(bal) - 1;
                float ud = __shfl_up_sync(0xffffffffu, best_d, 1);
                int   ui = __shfl_up_sync(0xffffffffu, best_i, 1);
                if (lane > pos)       { best_d = ud; best_i = ui; }
                else if (lane == pos) { best_d = dc; best_i = j0 + src; }
            }
        }
        thr = __shfl_sync(0xffffffffu, best_d, 31);
    }
    g_nn[(size_t)q*KNB + lane] = best_i;
}

// -------- GEMM layer via mma.sync bf16 (3-term split), M=128/CTA --------
// Epilogue fuses BN stats (always) and, for POOL=1, per-query max/min (no y write).
template<int KPAD, int CIN, int N, int MODE, int POOL>
__global__ __launch_bounds__(256) void gemm_kernel(
        const float* __restrict__ feat, const float* __restrict__ xyz,
        const float* __restrict__ qxyz, const float* __restrict__ y_in,
        const float* __restrict__ W,    float* __restrict__ y_out, int prev)
{
    extern __shared__ char smem[];
    constexpr int ST = KPAD + 8;
    constexpr int OFF_AH = 0;
    constexpr int OFF_AL = 128*ST*2;
    constexpr int OFF_BH = 2*OFF_AL;
    constexpr int OFF_BL = OFF_BH + N*ST*2;
    constexpr int OFF_S  = OFF_BL + N*ST*2;     // float ssum[N], ssq[N]
    float* ssum = (float*)(smem + OFF_S);
    float* ssq  = ssum + N;
    const uint32_t sb = smem_u32(smem);
    const int tid = threadIdx.x;
    const int n0  = blockIdx.x * 128;
    const int cq  = tid & 15, rs = tid >> 4;

    if (tid < N) { ssum[tid] = 0.f; ssq[tid] = 0.f; }

    if (MODE == 0) {
        uint4 z = make_uint4(0,0,0,0);
        if (tid < 128 + N) {
            int isA = tid < 128;
            int row = isA ? tid : tid - 128;
            char* base = smem + (isA ? OFF_AH : OFF_BH) + row*ST*2 + 128;
            char* basl = smem + (isA ? OFF_AL : OFF_BL) + row*ST*2 + 128;
            *(uint4*)(base) = z;      *(uint4*)(base + 16) = z;
            *(uint4*)(basl) = z;      *(uint4*)(basl + 16) = z;
        }
        #pragma unroll
        for (int it = 0; it < 8; it++) {
            int row = rs + 16*it;
            int n   = n0 + row;
            int b   = n >> 16;
            int nn  = g_nn[n];
            float4 f = *(const float4*)(feat + (size_t)(b*P1 + nn)*64 + 4*cq);
            uint2 H, L; split4(f, H, L);
            *(uint2*)(smem + OFF_AH + row*ST*2 + 8*cq) = H;
            *(uint2*)(smem + OFF_AL + row*ST*2 + 8*cq) = L;
            if (cq == 0) {
                int q = n >> 5;
                const float* nx = xyz  + (size_t)(b*P1 + nn)*3;
                const float* qp = qxyz + (size_t)q*3;
                #pragma unroll
                for (int j = 0; j < 3; j++) {
                    __nv_bfloat16 h, l; split1(__fsub_rn(nx[j], qp[j]), h, l);
                    *(__nv_bfloat16*)(smem + OFF_AH + row*ST*2 + 128 + 2*j) = h;
                    *(__nv_bfloat16*)(smem + OFF_AL + row*ST*2 + 128 + 2*j) = l;
                }
            }
        }
        #pragma unroll
        for (int it = 0; it < N/16; it++) {
            int o = rs + 16*it;
            const float* wr = W + (size_t)o*CIN;
            float4 w4 = make_float4(wr[4*cq], wr[4*cq+1], wr[4*cq+2], wr[4*cq+3]);
            uint2 H, L; split4(w4, H, L);
            *(uint2*)(smem + OFF_BH + o*ST*2 + 8*cq) = H;
            *(uint2*)(smem + OFF_BL + o*ST*2 + 8*cq) = L;
            if (cq == 0) {
                #pragma unroll
                for (int j = 0; j < 3; j++) {
                    __nv_bfloat16 h, l; split1(wr[64 + j], h, l);
                    *(__nv_bfloat16*)(smem + OFF_BH + o*ST*2 + 128 + 2*j) = h;
                    *(__nv_bfloat16*)(smem + OFF_BL + o*ST*2 + 128 + 2*j) = l;
                }
            }
        }
    } else {
        const float4 sc4 = *(const float4*)(g_scale[prev] + 4*cq);
        const float4 sh4 = *(const float4*)(g_shift[prev] + 4*cq);
        #pragma unroll
        for (int it = 0; it < 8; it++) {
            int row = rs + 16*it;
            float4 v = *(const float4*)(y_in + (size_t)(n0 + row)*64 + 4*cq);
            v.x = fmaxf(__fmaf_rn(sc4.x, v.x, sh4.x), 0.f);
            v.y = fmaxf(__fmaf_rn(sc4.y, v.y, sh4.y), 0.f);
            v.z = fmaxf(__fmaf_rn(sc4.z, v.z, sh4.z), 0.f);
            v.w = fmaxf(__fmaf_rn(sc4.w, v.w, sh4.w), 0.f);
            uint2 H, L; split4(v, H, L);
            *(uint2*)(smem + OFF_AH + row*ST*2 + 8*cq) = H;
            *(uint2*)(smem + OFF_AL + row*ST*2 + 8*cq) = L;
        }
        #pragma unroll
        for (int it = 0; it < N/16; it++) {
            int o = rs + 16*it;
            float4 w4 = *(const float4*)(W + (size_t)o*64 + 4*cq);
            uint2 H, L; split4(w4, H, L);
            *(uint2*)(smem + OFF_BH + o*ST*2 + 8*cq) = H;
            *(uint2*)(smem + OFF_BL + o*ST*2 + 8*cq) = L;
        }
    }
    __syncthreads();

    const int w = tid >> 5, lane = tid & 31;
    const int mw = w & 3, nw = w >> 2;          // warp: rows mw*32..+31 (one query), cols nw*(N/2)
    constexpr int NB = N/16;

    float acc[2][NB][4];
    #pragma unroll
    for (int mh = 0; mh < 2; mh++)
        #pragma unroll
        for (int nb = 0; nb < NB; nb++)
            #pragma unroll
            for (int j = 0; j < 4; j++) acc[mh][nb][j] = 0.f;

    const uint32_t aoff = ((mw*32 + (lane & 15))*ST + (lane >> 4)*8) * 2;
    const uint32_t boff = ((nw*(N/2) + (lane & 7))*ST + ((lane >> 3) & 1)*8) * 2;

    #pragma unroll
    for (int kk = 0; kk < KPAD/16; kk++) {
        uint32_t ah[2][4], al[2][4];
        #pragma unroll
        for (int mh = 0; mh < 2; mh++) {
            ldsm4(ah[mh], sb + OFF_AH + aoff + (mh*16*ST + kk*16)*2);
            ldsm4(al[mh], sb + OFF_AL + aoff + (mh*16*ST + kk*16)*2);
        }
        #pragma unroll
        for (int nb = 0; nb < NB; nb++) {
            uint32_t bh[2], bl[2];
            ldsm2(bh, sb + OFF_BH + boff + (nb*8*ST + kk*16)*2);
            ldsm2(bl, sb + OFF_BL + boff + (nb*8*ST + kk*16)*2);
            #pragma unroll
            for (int mh = 0; mh < 2; mh++) {
                mma16816(acc[mh][nb], ah[mh], bh);
                mma16816(acc[mh][nb], ah[mh], bl);
                mma16816(acc[mh][nb], al[mh], bh);
            }
        }
    }

    const int g = lane >> 2, t = lane & 3;
    #pragma unroll
    for (int nb = 0; nb < NB; nb++) {
        // per-lane partials over its 4 rows, per column (2t, 2t+1)
        float s0 = acc[0][nb][0] + acc[0][nb][2] + acc[1][nb][0] + acc[1][nb][2];
        float s1 = acc[0][nb][1] + acc[0][nb][3] + acc[1][nb][1] + acc[1][nb][3];
        float q0 = acc[0][nb][0]*acc[0][nb][0] + acc[0][nb][2]*acc[0][nb][2]
                 + acc[1][nb][0]*acc[1][nb][0] + acc[1][nb][2]*acc[1][nb][2];
        float q1 = acc[0][nb][1]*acc[0][nb][1] + acc[0][nb][3]*acc[0][nb][3]
                 + acc[1][nb][1]*acc[1][nb][1] + acc[1][nb][3]*acc[1][nb][3];
        float mx0, mn0, mx1, mn1;
        if (POOL) {
            mx0 = fmaxf(fmaxf(acc[0][nb][0], acc[0][nb][2]), fmaxf(acc[1][nb][0], acc[1][nb][2]));
            mn0 = fminf(fminf(acc[0][nb][0], acc[0][nb][2]), fminf(acc[1][nb][0], acc[1][nb][2]));
            mx1 = fmaxf(fmaxf(acc[0][nb][1], acc[0][nb][3]), fmaxf(acc[1][nb][1], acc[1][nb][3]));
            mn1 = fminf(fminf(acc[0][nb][1], acc[0][nb][3]), fminf(acc[1][nb][1], acc[1][nb][3]));
        }
        #pragma unroll
        for (int off = 4; off < 32; off <<= 1) {
            s0 += __shfl_xor_sync(0xffffffffu, s0, off);
            s1 += __shfl_xor_sync(0xffffffffu, s1, off);
            q0 += __shfl_xor_sync(0xffffffffu, q0, off);
            q1 += __shfl_xor_sync(0xffffffffu, q1, off);
            if (POOL) {
                mx0 = fmaxf(mx0, __shfl_xor_sync(0xffffffffu, mx0, off));
                mn0 = fminf(mn0, __shfl_xor_sync(0xffffffffu, mn0, off));
                mx1 = fmaxf(mx1, __shfl_xor_sync(0xffffffffu, mx1, off));
                mn1 = fminf(mn1, __shfl_xor_sync(0xffffffffu, mn1, off));
            }
        }
        if (g == 0) {
            int col = nw*(N/2) + nb*8 + 2*t;
            atomicAdd(&ssum[col],   s0); atomicAdd(&ssum[col+1], s1);
            atomicAdd(&ssq[col],    q0); atomicAdd(&ssq[col+1],  q1);
            if (POOL) {
                int q = blockIdx.x*4 + mw;
                g_mx[(size_t)q*128 + col]   = mx0;  g_mn[(size_t)q*128 + col]   = mn0;
                g_mx[(size_t)q*128 + col+1] = mx1;  g_mn[(size_t)q*128 + col+1] = mn1;
            }
        }
    }

    if (!POOL) {
        #pragma unroll
        for (int mh = 0; mh < 2; mh++) {
            #pragma unroll
            for (int nb = 0; nb < NB; nb++) {
                int row = n0 + mw*32 + mh*16 + g;
                int col = nw*(N/2) + nb*8 + 2*t;
                *(float2*)(y_out + (size_t)row*N + col)       = make_float2(acc[mh][nb][0], acc[mh][nb][1]);
                *(float2*)(y_out + (size_t)(row + 8)*N + col) = make_float2(acc[mh][nb][2], acc[mh][nb][3]);
            }
        }
    }

    __syncthreads();
    if (tid < N) {
        atomicAdd(&g_sum[tid],   (double)ssum[tid]);
        atomicAdd(&g_sqsum[tid], (double)ssq[tid]);
    }
}

// -------- BN finalize (bias absorbed by mean subtraction) --------
__global__ void finalize_kernel(const float* __restrict__ gamma,
                                const float* __restrict__ beta,
                                int layer) {
    int o = threadIdx.x;
    double mean = g_sum[o]   * (1.0 / (double)NTOT);
    double var  = g_sqsum[o] * (1.0 / (double)NTOT) - mean*mean;
    float sc = gamma[o] * (float)(1.0 / sqrt(var + 1e-5));
    g_scale[layer][o] = sc;
    g_shift[layer][o] = __fmaf_rn(-(float)mean, sc, beta[o]);
    g_sum[o] = 0.0; g_sqsum[o] = 0.0;
}

// -------- final affine+relu on pooled max/min --------
__global__ void pool_apply_kernel(float* __restrict__ out) {
    int idx = blockIdx.x * 256 + threadIdx.x;
    int o = idx & 127;
    float sc = g_scale[2][o], sh = g_shift[2][o];
    float vmx = __fmaf_rn(sc, g_mx[idx], sh);
    float vmn = __fmaf_rn(sc, g_mn[idx], sh);
    out[idx] = fmaxf(fmaxf(vmx, vmn), 0.f);
}

extern "C" void kernel_launch(void* const* d_in, const int* in_sizes, int n_in,
                              void* d_out, int out_size) {
    const float* xyz  = (const float*)d_in[0];
    const float* feat = (const float*)d_in[1];
    const int*   sidx = (const int*)d_in[2];
    const float *w1=(const float*)d_in[3],
                *g1=(const float*)d_in[5],  *t1=(const float*)d_in[6];
    const float *w2=(const float*)d_in[7],
                *g2=(const float*)d_in[9],  *t2=(const float*)d_in[10];
    const float *w3=(const float*)d_in[11],
                *g3=(const float*)d_in[13], *t3=(const float*)d_in[14];
    float* out      = (float*)d_out;
    float* new_xyz  = out;
    float* new_feat = out + NQ*3;

    float* bufA; cudaGetSymbolAddress((void**)&bufA, g_bufA);
    float* bufB; cudaGetSymbolAddress((void**)&bufB, g_bufB);

    const int S1 = (256 + 128) * (80+8) * 2 + 64*8;    // 68096
    const int S2 = (256 + 128) * (64+8) * 2 + 64*8;    // 55808
    const int S3 = (256 + 256) * (64+8) * 2 + 128*8;   // 74752
    cudaFuncSetAttribute(knn_kernel, cudaFuncAttributeMaxDynamicSharedMemorySize, 131072);
    cudaFuncSetAttribute(gemm_kernel<80,67,64,0,0>,  cudaFuncAttributeMaxDynamicSharedMemorySize, S1);
    cudaFuncSetAttribute(gemm_kernel<64,64,64,1,0>,  cudaFuncAttributeMaxDynamicSharedMemorySize, S2);
    cudaFuncSetAttribute(gemm_kernel<64,64,128,1,1>, cudaFuncAttributeMaxDynamicSharedMemorySize, S3);

    knn_kernel<<<NQ/32, 1024, 131072>>>(xyz, sidx, new_xyz);
    gemm_kernel<80,67,64,0,0><<<NTOT/128, 256, S1>>>(feat, xyz, new_xyz, nullptr, w1, bufA, 0);
    finalize_kernel<<<1,64>>>(g1, t1, 0);
    gemm_kernel<64,64,64,1,0><<<NTOT/128, 256, S2>>>(nullptr, nullptr, nullptr, bufA, w2, bufB, 0);
    finalize_kernel<<<1,64>>>(g2, t2, 1);
    gemm_kernel<64,64,128,1,1><<<NTOT/128, 256, S3>>>(nullptr, nullptr, nullptr, bufB, w3, nullptr, 1);
    finalize_kernel<<<1,128>>>(g3, t3, 2);
    pool_apply_kernel<<<(NQ*128)/256, 256>>>(new_feat);
}